// round 6
// baseline (speedup 1.0000x reference)
#include <cuda_runtime.h>
#include <math.h>

// ---------------------------------------------------------------------------
// InvariantPolynomial: out = SILU_CST * sum_e x_left[oi[e]] * x_right[e] * f(|pos_e|)
// R5 lesson: kernel was L1tex-WAVEFRONT-bound: random table gathers cost
// ~28 wavefronts/LDG x 8 per warp-unit. Fix: f-table as float2 pairs in SMEM
// (LDS bank conflicts ~4 instead of 28 wavefronts), occupancy 48%->75%.
// ---------------------------------------------------------------------------

#define TABLE_N 4096                // intervals; entries 0..TABLE_N
#define D_MAX   5.25f               // f==0 (fp32 underflow of all emb) for d >= ~4.8
#define QH      (24.0f / 8192.0f)   // quadrature step (exact)
#define NTB     17                  // 17*256 = 4352 >= 4097 table entries
#define NQBK    32                  // 32*256 = 8192 quad pts (+ endpoint)
#define NSETUP  (NTB + NQBK)
#define MAXG    4096

__device__ float    g_tab[TABLE_N + 1];
__device__ float    g_qpart[NQBK + 1];
__device__ double   g_mpart[MAXG];
__device__ unsigned g_arrive;       // monotone across graph replays
__device__ unsigned g_done;         // monotone across graph replays

__device__ __forceinline__ float silu_f(float p) {
    return __fdividef(p, 1.0f + __expf(-p));
}

__global__ void __launch_bounds__(256, 6)
fused_kernel(const float4* __restrict__ pos4,
             const float4* __restrict__ xr4,
             const int4*   __restrict__ idx4,
             const float*  __restrict__ xleft,
             const float*  __restrict__ W1,
             const float*  __restrict__ W2,
             float* __restrict__ out,
             int nq, int G) {
    const int bid = blockIdx.x, tid = threadIdx.x;
    __shared__ float2 stab[TABLE_N];        // 32 KB: (f[i], f[i+1]) pairs

    // ===================== phase 1: setup slices =====================
    if (bid < NTB) {
        // ---- f(d) table entries, one per thread ----
        __shared__ float sW1[600];          // W1 [20,30] row-major
        __shared__ float sW2s[30];          // rowsum(W2)/sqrt(30)
        for (int i = tid; i < 600; i += 256) sW1[i] = W1[i];
        if (tid < 30) {
            float s = 0.f;
            #pragma unroll
            for (int c = 0; c < 5; c++) s += W2[tid * 5 + c];
            sW2s[tid] = s * 0.18257418583505536f;       // 1/sqrt(30)
        }
        __syncthreads();

        int i = bid * 256 + tid;                        // 0..4351 (use 0..4096)
        if (i <= TABLE_N) {
            float d = (float)i * (D_MAX / (float)TABLE_N);
            float e[20];
            #pragma unroll
            for (int k = 0; k < 20; k++) {
                float vk   = (float)(k + 1) * (3.5f / 21.0f);
                float diff = (d - vk) * (21.0f / 3.5f);
                e[k] = __expf(-diff * diff) * (1.0f / 1.12f);
            }
            float pre[30];
            #pragma unroll
            for (int j = 0; j < 30; j++) pre[j] = 0.f;
            #pragma unroll
            for (int k = 0; k < 20; k++) {
                #pragma unroll
                for (int j = 0; j < 30; j++) pre[j] = fmaf(e[k], sW1[k * 30 + j], pre[j]);
            }
            float f = 0.f;
            #pragma unroll
            for (int j = 0; j < 30; j++) {
                float p = pre[j] * 0.22360679774997896f;   // 1/sqrt(20)
                f = fmaf(silu_f(p), sW2s[j], f);
            }
            g_tab[i] = f;
        }
    } else if (bid < NSETUP) {
        // ---- trapezoid quadrature for silu normalize2mom ----
        __shared__ float sred[256];
        int   i = (bid - NTB) * 256 + tid;              // 0..8191
        float z   = fmaf((float)i, QH, -12.0f);
        float s   = silu_f(z);
        float phi = 0.3989422804014327f * __expf(-0.5f * z * z);
        float v   = s * s * phi;
        if (i == 0) v *= 0.5f;                          // left endpoint weight
        sred[tid] = v;
        __syncthreads();
        #pragma unroll
        for (int st = 128; st > 0; st >>= 1) {
            if (tid < st) sred[tid] += sred[tid + st];
            __syncthreads();
        }
        if (tid == 0) g_qpart[bid - NTB] = sred[0];
        if (bid == NTB && tid == 1) {                   // right endpoint z=+12
            float s2   = silu_f(12.0f);
            float phi2 = 0.3989422804014327f * __expf(-0.5f * 144.0f);
            g_qpart[NQBK] = 0.5f * s2 * s2 * phi2;
        }
    }

    // ===================== grid barrier (replay-safe monotone) ==============
    __threadfence();
    __shared__ unsigned goal_s;
    if (tid == 0) {
        unsigned old = atomicAdd(&g_arrive, 1u);
        goal_s = (old / (unsigned)G + 1u) * (unsigned)G;
    }
    __syncthreads();
    if (tid == 0) {
        unsigned goal = goal_s;
        while (*((volatile unsigned*)&g_arrive) < goal) __nanosleep(64);
    }
    __syncthreads();
    __threadfence();

    // ---- fill this block's SMEM table (L2-resident source, coalesced) ----
    for (int i = tid; i < TABLE_N; i += 256)
        stab[i] = make_float2(g_tab[i], g_tab[i + 1]);
    __syncthreads();

    // ===================== phase 2: main pass =====================
    const float scale = (float)TABLE_N / D_MAX;
    float local = 0.f;
    for (int t = bid * 256 + tid; t < nq; t += G * 256) {
        float4 a = pos4[3 * t];
        float4 b = pos4[3 * t + 1];
        float4 c = pos4[3 * t + 2];
        float4 w = xr4[t];
        int4  id = idx4[t];

        float d0 = sqrtf(fmaf(a.x, a.x, fmaf(a.y, a.y, a.z * a.z)));
        float d1 = sqrtf(fmaf(a.w, a.w, fmaf(b.x, b.x, b.y * b.y)));
        float d2 = sqrtf(fmaf(b.z, b.z, fmaf(b.w, b.w, c.x * c.x)));
        float d3 = sqrtf(fmaf(c.y, c.y, fmaf(c.z, c.z, c.w * c.w)));

        float t0 = fminf(d0 * scale, (float)TABLE_N - 0.5f);
        float t1 = fminf(d1 * scale, (float)TABLE_N - 0.5f);
        float t2 = fminf(d2 * scale, (float)TABLE_N - 0.5f);
        float t3 = fminf(d3 * scale, (float)TABLE_N - 0.5f);
        int i0 = (int)t0, i1 = (int)t1, i2 = (int)t2, i3 = (int)t3;

        float2 p0 = stab[i0];
        float2 p1 = stab[i1];
        float2 p2 = stab[i2];
        float2 p3 = stab[i3];

        float g0 = __ldg(&xleft[id.x]);
        float g1 = __ldg(&xleft[id.y]);
        float g2 = __ldg(&xleft[id.z]);
        float g3 = __ldg(&xleft[id.w]);

        float f0 = fmaf(t0 - (float)i0, p0.y - p0.x, p0.x);
        float f1 = fmaf(t1 - (float)i1, p1.y - p1.x, p1.x);
        float f2 = fmaf(t2 - (float)i2, p2.y - p2.x, p2.x);
        float f3 = fmaf(t3 - (float)i3, p3.y - p3.x, p3.x);

        local += f0 * w.x * g0;
        local += f1 * w.y * g1;
        local += f2 * w.z * g2;
        local += f3 * w.w * g3;
    }

    // block reduction -> per-block double partial
    #pragma unroll
    for (int o = 16; o > 0; o >>= 1)
        local += __shfl_down_sync(0xffffffffu, local, o);
    __shared__ float warpsum[8];
    int lane = tid & 31, wid = tid >> 5;
    if (lane == 0) warpsum[wid] = local;
    __syncthreads();
    if (wid == 0) {
        float v = (lane < 8) ? warpsum[lane] : 0.f;
        #pragma unroll
        for (int o = 4; o > 0; o >>= 1)
            v += __shfl_down_sync(0xffffffffu, v, o);
        if (lane == 0) g_mpart[bid] = (double)v;
    }

    // ===================== phase 3: last block finalizes =====================
    __threadfence();
    __shared__ unsigned last_s;
    if (tid == 0) {
        unsigned tk = atomicAdd(&g_done, 1u);
        last_s = ((tk % (unsigned)G) == (unsigned)(G - 1)) ? 1u : 0u;
    }
    __syncthreads();
    if (!last_s) return;

    __threadfence();
    __shared__ double redm[256], redq[256];
    double m = 0.0, q = 0.0;
    for (int i = tid; i < G; i += 256) m += ((volatile double*)g_mpart)[i];
    for (int i = tid; i <= NQBK; i += 256) q += (double)((volatile float*)g_qpart)[i];
    redm[tid] = m;
    redq[tid] = q;
    __syncthreads();
    #pragma unroll
    for (int s = 128; s > 0; s >>= 1) {
        if (tid < s) { redm[tid] += redm[tid + s]; redq[tid] += redq[tid + s]; }
        __syncthreads();
    }
    if (tid == 0) {
        double integral = (double)QH * redq[0];
        double cst = 1.0 / sqrt(integral);              // ~1.679 silu normalize2mom
        out[0] = (float)(redm[0] * cst);
    }
}

// ---------------------------------------------------------------------------
// Tail kernel handles E % 4 != 0 edges (E = 2M is divisible; defensive only).
// Runs before fused_kernel's finalize? No -- tail folded via nq rounding up is
// unsafe; instead require E % 4 handling here: we add tail into g_mpart[0]? 
// Simplest correct approach: process tail inside fused kernel block 0 -- but
// E is known divisible by 4 for this dataset; still, guard via scalar loop in
// host-selected block below.
// ---------------------------------------------------------------------------

extern "C" void kernel_launch(void* const* d_in, const int* in_sizes, int n_in,
                              void* d_out, int out_size) {
    const float* pos = (const float*)d_in[0];   // [E,3]
    const float* xr  = (const float*)d_in[1];   // [E,1]
    const float* xl  = (const float*)d_in[2];   // [N,1]
    const float* W1  = (const float*)d_in[3];   // [20,30]
    const float* W2  = (const float*)d_in[4];   // [30,5]
    const int*   oi  = (const int*)d_in[5];     // [E]

    int E = in_sizes[1];
    if (E < 0) E = 0;
    int nq = E / 4;                             // E == 2,000,000: no tail

    int dev = 0;  cudaGetDevice(&dev);
    int nsm = 0;  cudaDeviceGetAttribute(&nsm, cudaDevAttrMultiProcessorCount, dev);
    int bpm = 0;
    cudaOccupancyMaxActiveBlocksPerMultiprocessor(&bpm, fused_kernel, 256, 0);
    if (nsm <= 0) nsm = 64;
    if (bpm <= 0) bpm = 1;
    long long g = (long long)nsm * bpm;
    int G = (g > MAXG) ? MAXG : (int)g;
    if (G < NSETUP) G = NSETUP;

    fused_kernel<<<G, 256>>>((const float4*)pos, (const float4*)xr,
                             (const int4*)oi, xl, W1, W2, (float*)d_out, nq, G);
}

// round 7
// speedup vs baseline: 1.2497x; 1.2497x over previous
#include <cuda_runtime.h>
#include <math.h>

// ---------------------------------------------------------------------------
// InvariantPolynomial: out = SILU_CST * sum_e x_left[oi[e]] * x_right[e] * f(|pos_e|)
// R6 lesson: SMEM table + persistent grid REGRESSED (LDS conflicts + slower
// persistent main loop). Revert to R4's measured-fast main pass.
// R7: (a) setup parallelized 4 lanes/table-entry (was latency-starved at
// 0.86 warps/scheduler), (b) final reduce merged into main kernel via ticket.
// ---------------------------------------------------------------------------

#define TABLE_N  8192
#define D_MAX    5.25f               // all 20 gaussian emb underflow in fp32 for d >= ~4.8
#define QH       (24.0f / 8192.0f)   // quadrature step (exactly representable)
#define TBLB     128                 // table blocks: 128*256/4 lanes = 8192 entries
#define NQBK     32                  // quad blocks: 32*256 = 8192 pts (+ endpoint)
#define MAXMB    8192                // max main-kernel blocks

__device__ float    g_tab[TABLE_N];
__device__ float    g_qpart[NQBK + 1];
__device__ double   g_mpart[MAXMB];
__device__ unsigned g_done;          // monotone across graph replays

__device__ __forceinline__ float silu_f(float p) {
    return __fdividef(p, 1.0f + __expf(-p));
}

// ---------------------------------------------------------------------------
// Setup: blocks [0,TBLB) table (4 lanes per entry); [TBLB, TBLB+NQBK) quad.
// ---------------------------------------------------------------------------
__global__ void __launch_bounds__(256) setup_kernel(const float* __restrict__ W1,
                                                    const float* __restrict__ W2) {
    const int tid = threadIdx.x;
    if (blockIdx.x < TBLB) {
        __shared__ float sW1[600];       // W1 [20,30] row-major
        __shared__ float sW2s[32];       // rowsum(W2)/sqrt(30), padded
        for (int i = tid; i < 600; i += 256) sW1[i] = W1[i];
        if (tid < 32) {
            float s = 0.f;
            if (tid < 30) {
                #pragma unroll
                for (int c = 0; c < 5; c++) s += W2[tid * 5 + c];
            }
            sW2s[tid] = s * 0.18257418583505536f;   // 1/sqrt(30); 0 for j>=30
        }
        __syncthreads();

        int gt  = blockIdx.x * 256 + tid;           // global thread
        int i   = gt >> 2;                          // table entry 0..8191
        int sub = gt & 3;                           // j-chunk 0..3 (8 units each)
        float d = (float)i * (D_MAX / (float)(TABLE_N - 1));

        float e[20];
        #pragma unroll
        for (int k = 0; k < 20; k++) {
            float vk   = (float)(k + 1) * (3.5f / 21.0f);
            float diff = (d - vk) * (21.0f / 3.5f);
            e[k] = __expf(-diff * diff) * (1.0f / 1.12f);
        }

        int j0 = sub * 8;                           // 0,8,16,24 (24..29 real, 30,31 pad=0)
        float pre[8];
        #pragma unroll
        for (int j = 0; j < 8; j++) pre[j] = 0.f;
        #pragma unroll
        for (int k = 0; k < 20; k++) {
            #pragma unroll
            for (int j = 0; j < 8; j++) {
                int jj = j0 + j;
                float wv = (jj < 30) ? sW1[k * 30 + jj] : 0.f;
                pre[j] = fmaf(e[k], wv, pre[j]);
            }
        }
        float f = 0.f;
        #pragma unroll
        for (int j = 0; j < 8; j++) {
            float p = pre[j] * 0.22360679774997896f;   // 1/sqrt(20)
            f = fmaf(silu_f(p), sW2s[j0 + j], f);      // pad lanes: sW2s==0
        }
        // reduce 4 lanes -> lane sub==0
        f += __shfl_xor_sync(0xffffffffu, f, 1);
        f += __shfl_xor_sync(0xffffffffu, f, 2);
        if (sub == 0) g_tab[i] = f;
        return;
    }

    // ---- trapezoid quadrature for silu normalize2mom ----
    __shared__ float sred[256];
    int   i = (blockIdx.x - TBLB) * 256 + tid;      // 0..8191
    float z   = fmaf((float)i, QH, -12.0f);
    float s   = silu_f(z);
    float phi = 0.3989422804014327f * __expf(-0.5f * z * z);
    float v   = s * s * phi;
    if (i == 0) v *= 0.5f;                          // left endpoint weight
    sred[tid] = v;
    __syncthreads();
    #pragma unroll
    for (int st = 128; st > 0; st >>= 1) {
        if (tid < st) sred[tid] += sred[tid + st];
        __syncthreads();
    }
    if (tid == 0) g_qpart[blockIdx.x - TBLB] = sred[0];
    if (blockIdx.x == TBLB && tid == 1) {           // right endpoint z = +12
        float s2   = silu_f(12.0f);
        float phi2 = 0.3989422804014327f * __expf(-0.5f * 144.0f);
        g_qpart[NQBK] = 0.5f * s2 * s2 * phi2;
    }
}

// ---------------------------------------------------------------------------
// Main pass (R4-identical inner loop) + in-kernel finalize via ticket.
// ---------------------------------------------------------------------------
__device__ __forceinline__ float edge_term(float x, float y, float z,
                                           float w, int id,
                                           const float* __restrict__ xleft) {
    float d  = sqrtf(fmaf(x, x, fmaf(y, y, z * z)));
    float ft = fminf(d * ((float)(TABLE_N - 1) / D_MAX), (float)(TABLE_N - 1));
    int   i  = min((int)ft, TABLE_N - 2);
    float f0 = g_tab[i];
    float f1 = g_tab[i + 1];
    float f  = fmaf(ft - (float)i, f1 - f0, f0);    // == 0 near/above D_MAX
    return f * w * __ldg(&xleft[id]);
}

__global__ void __launch_bounds__(256)
main_kernel(const float4* __restrict__ pos4,
            const float4* __restrict__ xr4,
            const int4*   __restrict__ idx4,
            const float*  __restrict__ xleft,
            const float*  __restrict__ pos,
            const float*  __restrict__ xr,
            const int*    __restrict__ idx,
            float* __restrict__ out,
            int nq, int E, int nb) {
    const int tid = threadIdx.x;
    float local = 0.f;
    for (int t = blockIdx.x * 256 + tid; t < nq; t += nb * 256) {
        float4 a = pos4[3 * t];
        float4 b = pos4[3 * t + 1];
        float4 c = pos4[3 * t + 2];
        float4 w = xr4[t];
        int4  id = idx4[t];
        local += edge_term(a.x, a.y, a.z, w.x, id.x, xleft);
        local += edge_term(a.w, b.x, b.y, w.y, id.y, xleft);
        local += edge_term(b.z, b.w, c.x, w.z, id.z, xleft);
        local += edge_term(c.y, c.z, c.w, w.w, id.w, xleft);
    }
    if (blockIdx.x == 0 && tid == 0) {              // tail edges (E % 4)
        for (int e2 = nq * 4; e2 < E; e2++)
            local += edge_term(pos[3 * e2], pos[3 * e2 + 1], pos[3 * e2 + 2],
                               xr[e2], idx[e2], xleft);
    }

    // block reduction -> per-block double partial
    #pragma unroll
    for (int o = 16; o > 0; o >>= 1)
        local += __shfl_down_sync(0xffffffffu, local, o);
    __shared__ float warpsum[8];
    int lane = tid & 31, wid = tid >> 5;
    if (lane == 0) warpsum[wid] = local;
    __syncthreads();
    if (wid == 0) {
        float v = (lane < 8) ? warpsum[lane] : 0.f;
        #pragma unroll
        for (int o = 4; o > 0; o >>= 1)
            v += __shfl_down_sync(0xffffffffu, v, o);
        if (lane == 0) g_mpart[blockIdx.x] = (double)v;
    }

    // ---- last-arriving block finalizes (replay-safe monotone ticket) ----
    __threadfence();
    __shared__ unsigned last_s;
    if (tid == 0) {
        unsigned tk = atomicAdd(&g_done, 1u);
        last_s = ((tk % (unsigned)nb) == (unsigned)(nb - 1)) ? 1u : 0u;
    }
    __syncthreads();
    if (!last_s) return;

    __threadfence();
    __shared__ double redm[256], redq[256];
    double m = 0.0, q = 0.0;
    for (int i = tid; i < nb; i += 256) m += ((volatile double*)g_mpart)[i];
    for (int i = tid; i <= NQBK; i += 256) q += (double)((volatile float*)g_qpart)[i];
    redm[tid] = m;
    redq[tid] = q;
    __syncthreads();
    #pragma unroll
    for (int s = 128; s > 0; s >>= 1) {
        if (tid < s) { redm[tid] += redm[tid + s]; redq[tid] += redq[tid + s]; }
        __syncthreads();
    }
    if (tid == 0) {
        double integral = (double)QH * redq[0];
        double cst = 1.0 / sqrt(integral);          // ~1.679 silu normalize2mom
        out[0] = (float)(redm[0] * cst);
    }
}

// ---------------------------------------------------------------------------
extern "C" void kernel_launch(void* const* d_in, const int* in_sizes, int n_in,
                              void* d_out, int out_size) {
    const float* pos = (const float*)d_in[0];   // [E,3]
    const float* xr  = (const float*)d_in[1];   // [E,1]
    const float* xl  = (const float*)d_in[2];   // [N,1]
    const float* W1  = (const float*)d_in[3];   // [20,30]
    const float* W2  = (const float*)d_in[4];   // [30,5]
    const int*   oi  = (const int*)d_in[5];     // [E]

    int E = in_sizes[1];
    if (E < 0) E = 0;
    int nq = E / 4;

    setup_kernel<<<TBLB + NQBK, 256>>>(W1, W2);

    int nb = (nq + 255) / 256;
    if (nb < 1) nb = 1;
    if (nb > MAXMB) nb = MAXMB;
    main_kernel<<<nb, 256>>>((const float4*)pos, (const float4*)xr,
                             (const int4*)oi, xl, pos, xr, oi,
                             (float*)d_out, nq, E, nb);
}

// round 8
// speedup vs baseline: 1.2785x; 1.0230x over previous
#include <cuda_runtime.h>
#include <math.h>

// ---------------------------------------------------------------------------
// InvariantPolynomial: out = SILU_CST * sum_e x_left[oi[e]] * x_right[e] * f(|pos_e|)
// R7 measurement: main pass is L1tex-WAVEFRONT-bound (~350 wf per 4-edge
// warp-unit; table gathers = ~200 of them). R8: 2048-interval f-table as
// float2 pairs in 16KB SMEM per block (cheap fill, smem-crossbar gathers),
// keeping R7's fast setup + in-kernel finalize. Predicted rel_err ~5e-5.
// ---------------------------------------------------------------------------

#define TABLE_N  2048                // intervals; g_tab has TABLE_N+1 entries
#define D_MAX    5.25f               // all 20 gaussian emb underflow in fp32 for d >= ~4.8
#define QH       (24.0f / 8192.0f)   // quadrature step (exactly representable)
#define TBLB     33                  // (TABLE_N+1)*4 lanes = 8196 thr -> 33 blocks
#define NQBK     32                  // 32*256 = 8192 quad pts (+ endpoint)
#define MAXMB    8192

__device__ float    g_tab[TABLE_N + 1];
__device__ float    g_qpart[NQBK + 1];
__device__ double   g_mpart[MAXMB];
__device__ unsigned g_done;          // monotone across graph replays

__device__ __forceinline__ float silu_f(float p) {
    return __fdividef(p, 1.0f + __expf(-p));
}

// ---------------------------------------------------------------------------
// Setup: blocks [0,TBLB) table (4 lanes per entry); [TBLB, TBLB+NQBK) quad.
// ---------------------------------------------------------------------------
__global__ void __launch_bounds__(256) setup_kernel(const float* __restrict__ W1,
                                                    const float* __restrict__ W2) {
    const int tid = threadIdx.x;
    if (blockIdx.x < TBLB) {
        __shared__ float sW1[600];       // W1 [20,30] row-major
        __shared__ float sW2s[32];       // rowsum(W2)/sqrt(30), padded with 0
        for (int i = tid; i < 600; i += 256) sW1[i] = W1[i];
        if (tid < 32) {
            float s = 0.f;
            if (tid < 30) {
                #pragma unroll
                for (int c = 0; c < 5; c++) s += W2[tid * 5 + c];
            }
            sW2s[tid] = s * 0.18257418583505536f;   // 1/sqrt(30)
        }
        __syncthreads();

        int gt  = blockIdx.x * 256 + tid;
        int i   = gt >> 2;                          // table entry 0..2048
        int sub = gt & 3;                           // j-chunk (8 hidden units each)
        if (i > TABLE_N) return;
        float d = (float)i * (D_MAX / (float)TABLE_N);

        float e[20];
        #pragma unroll
        for (int k = 0; k < 20; k++) {
            float vk   = (float)(k + 1) * (3.5f / 21.0f);
            float diff = (d - vk) * (21.0f / 3.5f);
            e[k] = __expf(-diff * diff) * (1.0f / 1.12f);
        }

        int j0 = sub * 8;                           // 0,8,16,24 (30,31 pad=0)
        float pre[8];
        #pragma unroll
        for (int j = 0; j < 8; j++) pre[j] = 0.f;
        #pragma unroll
        for (int k = 0; k < 20; k++) {
            #pragma unroll
            for (int j = 0; j < 8; j++) {
                int jj = j0 + j;
                float wv = (jj < 30) ? sW1[k * 30 + jj] : 0.f;
                pre[j] = fmaf(e[k], wv, pre[j]);
            }
        }
        float f = 0.f;
        #pragma unroll
        for (int j = 0; j < 8; j++) {
            float p = pre[j] * 0.22360679774997896f;   // 1/sqrt(20)
            f = fmaf(silu_f(p), sW2s[j0 + j], f);
        }
        f += __shfl_xor_sync(0xffffffffu, f, 1);       // reduce 4 lanes
        f += __shfl_xor_sync(0xffffffffu, f, 2);
        if (sub == 0) g_tab[i] = f;
        return;
    }

    // ---- trapezoid quadrature for silu normalize2mom ----
    __shared__ float sred[256];
    int   i = (blockIdx.x - TBLB) * 256 + tid;      // 0..8191
    float z   = fmaf((float)i, QH, -12.0f);
    float s   = silu_f(z);
    float phi = 0.3989422804014327f * __expf(-0.5f * z * z);
    float v   = s * s * phi;
    if (i == 0) v *= 0.5f;
    sred[tid] = v;
    __syncthreads();
    #pragma unroll
    for (int st = 128; st > 0; st >>= 1) {
        if (tid < st) sred[tid] += sred[tid + st];
        __syncthreads();
    }
    if (tid == 0) g_qpart[blockIdx.x - TBLB] = sred[0];
    if (blockIdx.x == TBLB && tid == 1) {           // right endpoint z = +12
        float s2   = silu_f(12.0f);
        float phi2 = 0.3989422804014327f * __expf(-0.5f * 144.0f);
        g_qpart[NQBK] = 0.5f * s2 * s2 * phi2;
    }
}

// ---------------------------------------------------------------------------
// Main pass: SMEM float2 table, gathers off L1tex; in-kernel finalize.
// ---------------------------------------------------------------------------
__global__ void __launch_bounds__(256)
main_kernel(const float4* __restrict__ pos4,
            const float4* __restrict__ xr4,
            const int4*   __restrict__ idx4,
            const float*  __restrict__ xleft,
            const float*  __restrict__ pos,
            const float*  __restrict__ xr,
            const int*    __restrict__ idx,
            float* __restrict__ out,
            int nq, int E, int nb) {
    const int tid = threadIdx.x;
    __shared__ float2 stab[TABLE_N];                // 16 KB (f[i], f[i+1])

    // fill from L2-resident g_tab (coalesced, one-time)
    for (int i = tid; i < TABLE_N; i += 256)
        stab[i] = make_float2(g_tab[i], g_tab[i + 1]);
    __syncthreads();

    const float scale = (float)TABLE_N / D_MAX;
    float local = 0.f;
    for (int t = blockIdx.x * 256 + tid; t < nq; t += nb * 256) {
        float4 a = pos4[3 * t];
        float4 b = pos4[3 * t + 1];
        float4 c = pos4[3 * t + 2];
        float4 w = xr4[t];
        int4  id = idx4[t];

        float d0 = sqrtf(fmaf(a.x, a.x, fmaf(a.y, a.y, a.z * a.z)));
        float d1 = sqrtf(fmaf(a.w, a.w, fmaf(b.x, b.x, b.y * b.y)));
        float d2 = sqrtf(fmaf(b.z, b.z, fmaf(b.w, b.w, c.x * c.x)));
        float d3 = sqrtf(fmaf(c.y, c.y, fmaf(c.z, c.z, c.w * c.w)));

        float t0 = fminf(d0 * scale, (float)TABLE_N - 0.5f);
        float t1 = fminf(d1 * scale, (float)TABLE_N - 0.5f);
        float t2 = fminf(d2 * scale, (float)TABLE_N - 0.5f);
        float t3 = fminf(d3 * scale, (float)TABLE_N - 0.5f);
        int i0 = (int)t0, i1 = (int)t1, i2 = (int)t2, i3 = (int)t3;

        // launch the 4 L2 gathers early (independent of LDS)
        float g0 = __ldg(&xleft[id.x]);
        float g1 = __ldg(&xleft[id.y]);
        float g2 = __ldg(&xleft[id.z]);
        float g3 = __ldg(&xleft[id.w]);

        float2 p0 = stab[i0];
        float2 p1 = stab[i1];
        float2 p2 = stab[i2];
        float2 p3 = stab[i3];

        float f0 = fmaf(t0 - (float)i0, p0.y - p0.x, p0.x);
        float f1 = fmaf(t1 - (float)i1, p1.y - p1.x, p1.x);
        float f2 = fmaf(t2 - (float)i2, p2.y - p2.x, p2.x);
        float f3 = fmaf(t3 - (float)i3, p3.y - p3.x, p3.x);

        local += f0 * w.x * g0;
        local += f1 * w.y * g1;
        local += f2 * w.z * g2;
        local += f3 * w.w * g3;
    }
    if (blockIdx.x == 0 && tid == 0) {              // tail edges (E % 4)
        const float sc2 = (float)TABLE_N / D_MAX;
        for (int e2 = nq * 4; e2 < E; e2++) {
            float x = pos[3 * e2], y = pos[3 * e2 + 1], z = pos[3 * e2 + 2];
            float d  = sqrtf(fmaf(x, x, fmaf(y, y, z * z)));
            float ft = fminf(d * sc2, (float)TABLE_N - 0.5f);
            int   i  = (int)ft;
            float2 p = stab[i];
            float  f = fmaf(ft - (float)i, p.y - p.x, p.x);
            local += f * xr[e2] * __ldg(&xleft[idx[e2]]);
        }
    }

    // block reduction -> per-block double partial
    #pragma unroll
    for (int o = 16; o > 0; o >>= 1)
        local += __shfl_down_sync(0xffffffffu, local, o);
    __shared__ float warpsum[8];
    int lane = tid & 31, wid = tid >> 5;
    if (lane == 0) warpsum[wid] = local;
    __syncthreads();
    if (wid == 0) {
        float v = (lane < 8) ? warpsum[lane] : 0.f;
        #pragma unroll
        for (int o = 4; o > 0; o >>= 1)
            v += __shfl_down_sync(0xffffffffu, v, o);
        if (lane == 0) g_mpart[blockIdx.x] = (double)v;
    }

    // ---- last-arriving block finalizes (replay-safe monotone ticket) ----
    __threadfence();
    __shared__ unsigned last_s;
    if (tid == 0) {
        unsigned tk = atomicAdd(&g_done, 1u);
        last_s = ((tk % (unsigned)nb) == (unsigned)(nb - 1)) ? 1u : 0u;
    }
    __syncthreads();
    if (!last_s) return;

    __threadfence();
    __shared__ double redm[256], redq[256];
    double m = 0.0, q = 0.0;
    for (int i = tid; i < nb; i += 256) m += ((volatile double*)g_mpart)[i];
    for (int i = tid; i <= NQBK; i += 256) q += (double)((volatile float*)g_qpart)[i];
    redm[tid] = m;
    redq[tid] = q;
    __syncthreads();
    #pragma unroll
    for (int s = 128; s > 0; s >>= 1) {
        if (tid < s) { redm[tid] += redm[tid + s]; redq[tid] += redq[tid + s]; }
        __syncthreads();
    }
    if (tid == 0) {
        double integral = (double)QH * redq[0];
        double cst = 1.0 / sqrt(integral);          // ~1.679 silu normalize2mom
        out[0] = (float)(redm[0] * cst);
    }
}

// ---------------------------------------------------------------------------
extern "C" void kernel_launch(void* const* d_in, const int* in_sizes, int n_in,
                              void* d_out, int out_size) {
    const float* pos = (const float*)d_in[0];   // [E,3]
    const float* xr  = (const float*)d_in[1];   // [E,1]
    const float* xl  = (const float*)d_in[2];   // [N,1]
    const float* W1  = (const float*)d_in[3];   // [20,30]
    const float* W2  = (const float*)d_in[4];   // [30,5]
    const int*   oi  = (const int*)d_in[5];     // [E]

    int E = in_sizes[1];
    if (E < 0) E = 0;
    int nq = E / 4;

    setup_kernel<<<TBLB + NQBK, 256>>>(W1, W2);

    int nb = (nq + 255) / 256;
    if (nb < 1) nb = 1;
    if (nb > MAXMB) nb = MAXMB;
    main_kernel<<<nb, 256>>>((const float4*)pos, (const float4*)xr,
                             (const int4*)oi, xl, pos, xr, oi,
                             (float*)d_out, nq, E, nb);
}

// round 9
// speedup vs baseline: 1.5630x; 1.2225x over previous
#include <cuda_runtime.h>
#include <math.h>

// ---------------------------------------------------------------------------
// InvariantPolynomial: out = SILU_CST * sum_e x_left[oi[e]] * x_right[e] * f(|pos_e|)
// R8 lesson: SMEM table definitively falsified (slower than L1 gathers).
// R9: recombination of best-measured parts: R7's fast setup + R4's exact
// main kernel (global table, no ticket) + R4's separate final kernel.
// R2-R4 all measured main+final ~= 16us; R7/R8's ticket-fused main ~= 27us.
// ---------------------------------------------------------------------------

#define TABLE_N  8192
#define D_MAX    5.25f               // all 20 gaussian emb underflow in fp32 for d >= ~4.8
#define QH       (24.0f / 8192.0f)   // quadrature step (exactly representable)
#define TBLB     128                 // table blocks: 128*256/4 lanes = 8192 entries
#define NQBK     32                  // quad blocks: 32*256 = 8192 pts (+ endpoint)
#define MAXMB    8192

__device__ float  g_tab[TABLE_N];
__device__ float  g_qpart[NQBK + 1];
__device__ double g_mpart[MAXMB];

__device__ __forceinline__ float silu_f(float p) {
    return __fdividef(p, 1.0f + __expf(-p));
}

// ---------------------------------------------------------------------------
// Setup (R7 version): blocks [0,TBLB) table, 4 lanes/entry; then quad blocks.
// ---------------------------------------------------------------------------
__global__ void __launch_bounds__(256) setup_kernel(const float* __restrict__ W1,
                                                    const float* __restrict__ W2) {
    const int tid = threadIdx.x;
    if (blockIdx.x < TBLB) {
        __shared__ float sW1[600];       // W1 [20,30] row-major
        __shared__ float sW2s[32];       // rowsum(W2)/sqrt(30), padded with 0
        for (int i = tid; i < 600; i += 256) sW1[i] = W1[i];
        if (tid < 32) {
            float s = 0.f;
            if (tid < 30) {
                #pragma unroll
                for (int c = 0; c < 5; c++) s += W2[tid * 5 + c];
            }
            sW2s[tid] = s * 0.18257418583505536f;   // 1/sqrt(30)
        }
        __syncthreads();

        int gt  = blockIdx.x * 256 + tid;
        int i   = gt >> 2;                          // table entry 0..8191
        int sub = gt & 3;                           // j-chunk (8 hidden units)
        float d = (float)i * (D_MAX / (float)(TABLE_N - 1));

        float e[20];
        #pragma unroll
        for (int k = 0; k < 20; k++) {
            float vk   = (float)(k + 1) * (3.5f / 21.0f);
            float diff = (d - vk) * (21.0f / 3.5f);
            e[k] = __expf(-diff * diff) * (1.0f / 1.12f);
        }

        int j0 = sub * 8;                           // 0,8,16,24 (30,31 pad=0)
        float pre[8];
        #pragma unroll
        for (int j = 0; j < 8; j++) pre[j] = 0.f;
        #pragma unroll
        for (int k = 0; k < 20; k++) {
            #pragma unroll
            for (int j = 0; j < 8; j++) {
                int jj = j0 + j;
                float wv = (jj < 30) ? sW1[k * 30 + jj] : 0.f;
                pre[j] = fmaf(e[k], wv, pre[j]);
            }
        }
        float f = 0.f;
        #pragma unroll
        for (int j = 0; j < 8; j++) {
            float p = pre[j] * 0.22360679774997896f;   // 1/sqrt(20)
            f = fmaf(silu_f(p), sW2s[j0 + j], f);
        }
        f += __shfl_xor_sync(0xffffffffu, f, 1);       // reduce 4 lanes
        f += __shfl_xor_sync(0xffffffffu, f, 2);
        if (sub == 0) g_tab[i] = f;
        return;
    }

    // ---- trapezoid quadrature for silu normalize2mom ----
    __shared__ float sred[256];
    int   i = (blockIdx.x - TBLB) * 256 + tid;      // 0..8191
    float z   = fmaf((float)i, QH, -12.0f);
    float s   = silu_f(z);
    float phi = 0.3989422804014327f * __expf(-0.5f * z * z);
    float v   = s * s * phi;
    if (i == 0) v *= 0.5f;                          // left endpoint weight
    sred[tid] = v;
    __syncthreads();
    #pragma unroll
    for (int st = 128; st > 0; st >>= 1) {
        if (tid < st) sred[tid] += sred[tid + st];
        __syncthreads();
    }
    if (tid == 0) g_qpart[blockIdx.x - TBLB] = sred[0];
    if (blockIdx.x == TBLB && tid == 1) {           // right endpoint z = +12
        float s2   = silu_f(12.0f);
        float phi2 = 0.3989422804014327f * __expf(-0.5f * 144.0f);
        g_qpart[NQBK] = 0.5f * s2 * s2 * phi2;
    }
}

// ---------------------------------------------------------------------------
// Main pass: EXACT R4 kernel (global table, partial store, no ticket).
// ---------------------------------------------------------------------------
__device__ __forceinline__ float edge_term(float x, float y, float z,
                                           float w, int id,
                                           const float* __restrict__ xleft) {
    float d  = sqrtf(fmaf(x, x, fmaf(y, y, z * z)));
    float ft = fminf(d * ((float)(TABLE_N - 1) / D_MAX), (float)(TABLE_N - 1));
    int   i  = min((int)ft, TABLE_N - 2);
    float f0 = g_tab[i];
    float f1 = g_tab[i + 1];
    float f  = fmaf(ft - (float)i, f1 - f0, f0);    // == 0 near/above D_MAX
    return f * w * __ldg(&xleft[id]);
}

__global__ void __launch_bounds__(256)
main_kernel(const float4* __restrict__ pos4,
            const float4* __restrict__ xr4,
            const int4*   __restrict__ idx4,
            const float*  __restrict__ xleft,
            const float*  __restrict__ pos,
            const float*  __restrict__ xr,
            const int*    __restrict__ idx,
            int nq, int E) {
    float local = 0.f;
    for (int t = blockIdx.x * blockDim.x + threadIdx.x; t < nq;
         t += gridDim.x * blockDim.x) {
        float4 a = pos4[3 * t];
        float4 b = pos4[3 * t + 1];
        float4 c = pos4[3 * t + 2];
        float4 w = xr4[t];
        int4  id = idx4[t];
        local += edge_term(a.x, a.y, a.z, w.x, id.x, xleft);
        local += edge_term(a.w, b.x, b.y, w.y, id.y, xleft);
        local += edge_term(b.z, b.w, c.x, w.z, id.z, xleft);
        local += edge_term(c.y, c.z, c.w, w.w, id.w, xleft);
    }
    if (blockIdx.x == 0 && threadIdx.x == 0) {      // tail edges (E % 4)
        for (int e2 = nq * 4; e2 < E; e2++)
            local += edge_term(pos[3 * e2], pos[3 * e2 + 1], pos[3 * e2 + 2],
                               xr[e2], idx[e2], xleft);
    }

    // block reduction -> one double partial per block
    #pragma unroll
    for (int o = 16; o > 0; o >>= 1)
        local += __shfl_down_sync(0xffffffffu, local, o);
    __shared__ float warpsum[8];
    int lane = threadIdx.x & 31, wid = threadIdx.x >> 5;
    if (lane == 0) warpsum[wid] = local;
    __syncthreads();
    if (wid == 0) {
        float v = (lane < 8) ? warpsum[lane] : 0.f;
        #pragma unroll
        for (int o = 4; o > 0; o >>= 1)
            v += __shfl_down_sync(0xffffffffu, v, o);
        if (lane == 0) g_mpart[blockIdx.x] = (double)v;
    }
}

// ---------------------------------------------------------------------------
// Final: fixed-order parallel sums of both partial arrays, then scale.
// ---------------------------------------------------------------------------
__global__ void __launch_bounds__(256) final_kernel(float* __restrict__ out, int nmb) {
    __shared__ double redm[256], redq[256];
    double m = 0.0, q = 0.0;
    for (int i = threadIdx.x; i < nmb; i += 256) m += g_mpart[i];
    for (int i = threadIdx.x; i <= NQBK; i += 256) q += (double)g_qpart[i];
    redm[threadIdx.x] = m;
    redq[threadIdx.x] = q;
    __syncthreads();
    #pragma unroll
    for (int s = 128; s > 0; s >>= 1) {
        if (threadIdx.x < s) {
            redm[threadIdx.x] += redm[threadIdx.x + s];
            redq[threadIdx.x] += redq[threadIdx.x + s];
        }
        __syncthreads();
    }
    if (threadIdx.x == 0) {
        double integral = (double)QH * redq[0];
        double cst = 1.0 / sqrt(integral);          // ~1.679 silu normalize2mom
        out[0] = (float)(redm[0] * cst);
    }
}

// ---------------------------------------------------------------------------
extern "C" void kernel_launch(void* const* d_in, const int* in_sizes, int n_in,
                              void* d_out, int out_size) {
    const float* pos = (const float*)d_in[0];   // [E,3]
    const float* xr  = (const float*)d_in[1];   // [E,1]
    const float* xl  = (const float*)d_in[2];   // [N,1]
    const float* W1  = (const float*)d_in[3];   // [20,30]
    const float* W2  = (const float*)d_in[4];   // [30,5]
    const int*   oi  = (const int*)d_in[5];     // [E]

    int E = in_sizes[1];
    if (E < 0) E = 0;
    int nq = E / 4;

    setup_kernel<<<TBLB + NQBK, 256>>>(W1, W2);

    int nb = (nq + 255) / 256;
    if (nb < 1) nb = 1;
    if (nb > MAXMB) nb = MAXMB;
    main_kernel<<<nb, 256>>>((const float4*)pos, (const float4*)xr,
                             (const int4*)oi, xl, pos, xr, oi, nq, E);

    final_kernel<<<1, 256>>>((float*)d_out, nb);
}

// round 10
// speedup vs baseline: 1.6150x; 1.0332x over previous
#include <cuda_runtime.h>
#include <math.h>

// ---------------------------------------------------------------------------
// InvariantPolynomial: out = SILU_CST * sum_e x_left[oi[e]] * x_right[e] * f(|pos_e|)
// R9 baseline (23.9us). R10: table as float2 pairs in GLOBAL memory ->
// one LDG.64 per edge instead of two LDG.32 (halves table-gather L1tex
// wavefronts, the dominant budget term). Table 4096 intervals (rel ~1.9e-5).
// Structure otherwise identical to R9 (proven fastest).
// ---------------------------------------------------------------------------

#define TABLE_N  4096                // intervals; pair i covers [i, i+1]
#define D_MAX    5.25f               // all 20 gaussian emb underflow in fp32 for d >= ~4.8
#define QH       (24.0f / 8192.0f)   // quadrature step (exactly representable)
#define TBLB     65                  // (TABLE_N+1)*4 lanes = 16388 thr -> 65 blocks
#define NQBK     32                  // 32*256 = 8192 quad pts (+ endpoint)
#define MAXMB    8192

__device__ float2 g_tab2[TABLE_N];   // (f[i], f[i+1])
__device__ float  g_qpart[NQBK + 1];
__device__ double g_mpart[MAXMB];

__device__ __forceinline__ float silu_f(float p) {
    return __fdividef(p, 1.0f + __expf(-p));
}

// ---------------------------------------------------------------------------
// Setup: blocks [0,TBLB) table entries (4 lanes/entry, scatter into pairs);
// blocks [TBLB, TBLB+NQBK) quadrature.
// ---------------------------------------------------------------------------
__global__ void __launch_bounds__(256) setup_kernel(const float* __restrict__ W1,
                                                    const float* __restrict__ W2) {
    const int tid = threadIdx.x;
    if (blockIdx.x < TBLB) {
        __shared__ float sW1[600];       // W1 [20,30] row-major
        __shared__ float sW2s[32];       // rowsum(W2)/sqrt(30), padded with 0
        for (int i = tid; i < 600; i += 256) sW1[i] = W1[i];
        if (tid < 32) {
            float s = 0.f;
            if (tid < 30) {
                #pragma unroll
                for (int c = 0; c < 5; c++) s += W2[tid * 5 + c];
            }
            sW2s[tid] = s * 0.18257418583505536f;   // 1/sqrt(30)
        }
        __syncthreads();

        int gt  = blockIdx.x * 256 + tid;
        int i   = gt >> 2;                          // table entry 0..TABLE_N
        int sub = gt & 3;                           // j-chunk (8 hidden units)
        if (i > TABLE_N) return;
        float d = (float)i * (D_MAX / (float)TABLE_N);

        float e[20];
        #pragma unroll
        for (int k = 0; k < 20; k++) {
            float vk   = (float)(k + 1) * (3.5f / 21.0f);
            float diff = (d - vk) * (21.0f / 3.5f);
            e[k] = __expf(-diff * diff) * (1.0f / 1.12f);
        }

        int j0 = sub * 8;                           // 0,8,16,24 (30,31 pad=0)
        float pre[8];
        #pragma unroll
        for (int j = 0; j < 8; j++) pre[j] = 0.f;
        #pragma unroll
        for (int k = 0; k < 20; k++) {
            #pragma unroll
            for (int j = 0; j < 8; j++) {
                int jj = j0 + j;
                float wv = (jj < 30) ? sW1[k * 30 + jj] : 0.f;
                pre[j] = fmaf(e[k], wv, pre[j]);
            }
        }
        float f = 0.f;
        #pragma unroll
        for (int j = 0; j < 8; j++) {
            float p = pre[j] * 0.22360679774997896f;   // 1/sqrt(20)
            f = fmaf(silu_f(p), sW2s[j0 + j], f);
        }
        f += __shfl_xor_sync(0xffffffffu, f, 1);       // reduce 4 lanes
        f += __shfl_xor_sync(0xffffffffu, f, 2);
        if (sub == 0) {
            // scatter f[i] into the two pairs that reference it
            float* base = (float*)g_tab2;
            if (i < TABLE_N) base[2 * i] = f;          // pair i .x
            if (i >= 1)      base[2 * (i - 1) + 1] = f;// pair i-1 .y
        }
        return;
    }

    // ---- trapezoid quadrature for silu normalize2mom ----
    __shared__ float sred[256];
    int   i = (blockIdx.x - TBLB) * 256 + tid;      // 0..8191
    float z   = fmaf((float)i, QH, -12.0f);
    float s   = silu_f(z);
    float phi = 0.3989422804014327f * __expf(-0.5f * z * z);
    float v   = s * s * phi;
    if (i == 0) v *= 0.5f;                          // left endpoint weight
    sred[tid] = v;
    __syncthreads();
    #pragma unroll
    for (int st = 128; st > 0; st >>= 1) {
        if (tid < st) sred[tid] += sred[tid + st];
        __syncthreads();
    }
    if (tid == 0) g_qpart[blockIdx.x - TBLB] = sred[0];
    if (blockIdx.x == TBLB && tid == 1) {           // right endpoint z = +12
        float s2   = silu_f(12.0f);
        float phi2 = 0.3989422804014327f * __expf(-0.5f * 144.0f);
        g_qpart[NQBK] = 0.5f * s2 * s2 * phi2;
    }
}

// ---------------------------------------------------------------------------
// Main pass: R9 structure; table access is one LDG.64 (float2 pair).
// ---------------------------------------------------------------------------
__device__ __forceinline__ float edge_term(float x, float y, float z,
                                           float w, int id,
                                           const float* __restrict__ xleft) {
    float d  = sqrtf(fmaf(x, x, fmaf(y, y, z * z)));
    float ft = fminf(d * ((float)TABLE_N / D_MAX), (float)TABLE_N - 0.5f);
    int   i  = (int)ft;
    float2 p = __ldg(&g_tab2[i]);
    float  f = fmaf(ft - (float)i, p.y - p.x, p.x);  // == 0 near/above D_MAX
    return f * w * __ldg(&xleft[id]);
}

__global__ void __launch_bounds__(256)
main_kernel(const float4* __restrict__ pos4,
            const float4* __restrict__ xr4,
            const int4*   __restrict__ idx4,
            const float*  __restrict__ xleft,
            const float*  __restrict__ pos,
            const float*  __restrict__ xr,
            const int*    __restrict__ idx,
            int nq, int E) {
    float local = 0.f;
    for (int t = blockIdx.x * blockDim.x + threadIdx.x; t < nq;
         t += gridDim.x * blockDim.x) {
        float4 a = pos4[3 * t];
        float4 b = pos4[3 * t + 1];
        float4 c = pos4[3 * t + 2];
        float4 w = xr4[t];
        int4  id = idx4[t];
        local += edge_term(a.x, a.y, a.z, w.x, id.x, xleft);
        local += edge_term(a.w, b.x, b.y, w.y, id.y, xleft);
        local += edge_term(b.z, b.w, c.x, w.z, id.z, xleft);
        local += edge_term(c.y, c.z, c.w, w.w, id.w, xleft);
    }
    if (blockIdx.x == 0 && threadIdx.x == 0) {      // tail edges (E % 4)
        for (int e2 = nq * 4; e2 < E; e2++)
            local += edge_term(pos[3 * e2], pos[3 * e2 + 1], pos[3 * e2 + 2],
                               xr[e2], idx[e2], xleft);
    }

    // block reduction -> one double partial per block
    #pragma unroll
    for (int o = 16; o > 0; o >>= 1)
        local += __shfl_down_sync(0xffffffffu, local, o);
    __shared__ float warpsum[8];
    int lane = threadIdx.x & 31, wid = threadIdx.x >> 5;
    if (lane == 0) warpsum[wid] = local;
    __syncthreads();
    if (wid == 0) {
        float v = (lane < 8) ? warpsum[lane] : 0.f;
        #pragma unroll
        for (int o = 4; o > 0; o >>= 1)
            v += __shfl_down_sync(0xffffffffu, v, o);
        if (lane == 0) g_mpart[blockIdx.x] = (double)v;
    }
}

// ---------------------------------------------------------------------------
// Final: fixed-order parallel sums of both partial arrays, then scale.
// ---------------------------------------------------------------------------
__global__ void __launch_bounds__(256) final_kernel(float* __restrict__ out, int nmb) {
    __shared__ double redm[256], redq[256];
    double m = 0.0, q = 0.0;
    for (int i = threadIdx.x; i < nmb; i += 256) m += g_mpart[i];
    for (int i = threadIdx.x; i <= NQBK; i += 256) q += (double)g_qpart[i];
    redm[threadIdx.x] = m;
    redq[threadIdx.x] = q;
    __syncthreads();
    #pragma unroll
    for (int s = 128; s > 0; s >>= 1) {
        if (threadIdx.x < s) {
            redm[threadIdx.x] += redm[threadIdx.x + s];
            redq[threadIdx.x] += redq[threadIdx.x + s];
        }
        __syncthreads();
    }
    if (threadIdx.x == 0) {
        double integral = (double)QH * redq[0];
        double cst = 1.0 / sqrt(integral);          // ~1.679 silu normalize2mom
        out[0] = (float)(redm[0] * cst);
    }
}

// ---------------------------------------------------------------------------
extern "C" void kernel_launch(void* const* d_in, const int* in_sizes, int n_in,
                              void* d_out, int out_size) {
    const float* pos = (const float*)d_in[0];   // [E,3]
    const float* xr  = (const float*)d_in[1];   // [E,1]
    const float* xl  = (const float*)d_in[2];   // [N,1]
    const float* W1  = (const float*)d_in[3];   // [20,30]
    const float* W2  = (const float*)d_in[4];   // [30,5]
    const int*   oi  = (const int*)d_in[5];     // [E]

    int E = in_sizes[1];
    if (E < 0) E = 0;
    int nq = E / 4;

    setup_kernel<<<TBLB + NQBK, 256>>>(W1, W2);

    int nb = (nq + 255) / 256;
    if (nb < 1) nb = 1;
    if (nb > MAXMB) nb = MAXMB;
    main_kernel<<<nb, 256>>>((const float4*)pos, (const float4*)xr,
                             (const int4*)oi, xl, pos, xr, oi, nq, E);

    final_kernel<<<1, 256>>>((float*)d_out, nb);
}